// round 11
// baseline (speedup 1.0000x reference)
#include <cuda_runtime.h>
#include <cstdint>

// ---------------------------------------------------------------------------
// DisentanglementModule loss, closed form (TAU_POS == TAU_NEG => tau cancels):
//   loss_x = S_pos/c_pos - S_neg/c_neg
//   S_pos  = sum_g (n_g * q_g - ||m_g||^2) / d
//   S_all  = (B * Q - ||M||^2) / d ,  S_neg = S_all - S_pos
// Column-separable: per-column per-group sums (m) + sums-of-squares (q).
//
// Flattened column space: 384 float4 "slots", warp-aligned per matrix:
//   slots [0,256)    rep  (1024 cols)                 warps 0-7
//   slots [256,272)  act0 (64 cols); [272,288) pad    warp 8
//   slots [288,320)  act1 (128 cols)                  warp 9
//   slots [320,384)  act2 (256 cols)                  warps 10-11
//
// kA: grid (3,64). TMA bulk (cp.async.bulk + mbarrier ring, 4 stages x 4 rows)
//     streams rows into smem; threads consume their own 16B -> slot partials.
// kB: grid 48, slot-major reduce over 64 chunks (L2-resident scratch).
// kC: 1 block x 384 finalize.
// ---------------------------------------------------------------------------

#define NB      4096
#define NCHUNK  64
#define RPC     64                  // rows per chunk
#define NSLOT   384
#define NST     4                   // ring stages
#define RPS     4                   // rows per stage
#define NITER   (RPC / RPS)         // 16
#define KB_BLK  48
#define KB_PART 16
#define KB_CPP  (NCHUNK / KB_PART)  // 4
#define FULL    0xFFFFFFFFu

// Scratch: every element rewritten each launch -> graph-replay safe.
__device__ __align__(16) float4 g_Spart[NCHUNK * 4 * NSLOT]; // 1.6MB
__device__ float  g_Qpart[NCHUNK * 4 * NSLOT];               // 393KB
__device__ __align__(16) float4 g_S2[4 * NSLOT];             // 24KB
__device__ float  g_Q2[4 * NSLOT];                           // 6KB

#define F4Z make_float4(0.f, 0.f, 0.f, 0.f)
__device__ __forceinline__ void f4add(float4& a, const float4 b) {
    a.x += b.x; a.y += b.y; a.z += b.z; a.w += b.w;
}

// ---- TMA bulk + mbarrier primitives ----
#define MBAR_INIT(a, n) \
    asm volatile("mbarrier.init.shared.b64 [%0], %1;" :: "r"(a), "r"(n) : "memory")
#define MBAR_EXPECT_TX(a, b) \
    asm volatile("mbarrier.arrive.expect_tx.shared.b64 _, [%0], %1;" :: "r"(a), "r"(b) : "memory")
#define BULK1D(dst, src, bytes, mbar) \
    asm volatile("cp.async.bulk.shared::cta.global.mbarrier::complete_tx::bytes [%0], [%1], %2, [%3];" \
                 :: "r"(dst), "l"(src), "r"(bytes), "r"(mbar) : "memory")
__device__ __forceinline__ void mbar_wait(uint32_t mbar, uint32_t parity) {
    uint32_t done;
    asm volatile(
        "{\n\t.reg .pred p;\n\t"
        "mbarrier.try_wait.parity.acquire.cta.shared::cta.b64 p, [%1], %2;\n\t"
        "selp.b32 %0, 1, 0, p;\n\t}"
        : "=r"(done) : "r"(mbar), "r"(parity) : "memory");
    while (!done) {
        asm volatile(
            "{\n\t.reg .pred p;\n\t"
            "mbarrier.try_wait.parity.acquire.cta.shared::cta.b64 p, [%1], %2, 0x989680;\n\t"
            "selp.b32 %0, 1, 0, p;\n\t}"
            : "=r"(done) : "r"(mbar), "r"(parity) : "memory");
    }
}

// int64-vs-int32 detection: values in [0,3]; if int64 (LE), odd words are 0
// and even words <= 3. Vote over first 1024 pairs via __syncthreads_count.
__device__ __forceinline__ int detect_int64(const int* __restrict__ nl, int tid, int nthr) {
    int bad = 0;
    for (int i = tid; i < 1024; i += nthr) {
        const int lo = nl[2 * i], hi = nl[2 * i + 1];
        if (hi != 0 || (unsigned)lo > 3u) bad = 1;
    }
    return __syncthreads_count(bad) == 0;
}

// ---------------------------------------------------------------------------
// kA: TMA streaming. grid=(3, NCHUNK), 128 threads; thread = one slot.
// Stage buffer row layout (2KB/row):
//   x=0: rep[row, 0:512)  (2048B)      x=1: rep[row, 512:1024) (2048B)
//   x=2: [a0 256B][a1 512B][a2 1024B]  (1792B used)
// ---------------------------------------------------------------------------
#define ACC8(S, T, x) do {                                   \
    S.x += x.x; S.y += x.y; S.z += x.z; S.w += x.w;          \
    T.x = fmaf(x.x, x.x, T.x); T.y = fmaf(x.y, x.y, T.y);    \
    T.z = fmaf(x.z, x.z, T.z); T.w = fmaf(x.w, x.w, T.w); } while (0)

__global__ __launch_bounds__(128) void kA_partial(
    const float* __restrict__ rep, const float* __restrict__ a0,
    const float* __restrict__ a1,  const float* __restrict__ a2,
    const int* __restrict__ nl)
{
    __shared__ __align__(128) char buf[NST][RPS][2048];     // 32KB ring
    __shared__ __align__(8) uint64_t mbar_st[NST];
    __shared__ int gsh[RPC];

    const int tid   = threadIdx.x;
    const int bx    = blockIdx.x;
    const int slot  = bx * 128 + tid;
    const int chunk = blockIdx.y;
    const int row0  = chunk * RPC;

    const uint32_t mb0 = (uint32_t)__cvta_generic_to_shared(&mbar_st[0]);
    if (tid == 0) {
        #pragma unroll
        for (int s = 0; s < NST; s++) MBAR_INIT(mb0 + 8 * s, 1);
    }
    const int is64 = detect_int64(nl, tid, 128);  // barrier inside (orders init too)
    if (tid < RPC)
        gsh[tid] = (is64 ? nl[2 * (row0 + tid)] : nl[row0 + tid]) & 3;
    __syncthreads();

    // Consumer mapping: smem byte offset within a row buffer + activity.
    int soff, active = 1;
    if (bx < 2) soff = tid * 16;
    else if (tid < 16)  soff = tid * 16;                    // a0
    else if (tid < 32)  { soff = 0; active = 0; }           // pad
    else if (tid < 64)  soff = 256 + (tid - 32) * 16;       // a1
    else                soff = 768 + (tid - 64) * 16;       // a2

    const uint32_t sbase = (uint32_t)__cvta_generic_to_shared(&buf[0][0][0]);
    const uint32_t txbytes = (bx < 2) ? (RPS * 2048) : (RPS * 1792);

    // Producer: fill stage s with rows [j*RPS, (j+1)*RPS).
    auto fill = [&](int j, int s) {
        const uint32_t mb = mb0 + 8 * s;
        MBAR_EXPECT_TX(mb, txbytes);
        #pragma unroll
        for (int r = 0; r < RPS; r++) {
            const uint32_t dst = sbase + (uint32_t)((s * RPS + r) * 2048);
            const size_t row = (size_t)(row0 + j * RPS + r);
            if (bx < 2) {
                BULK1D(dst, rep + row * 1024 + bx * 512, 2048u, mb);
            } else {
                BULK1D(dst,       a0 + row * 512, 256u,  mb);
                BULK1D(dst + 256, a1 + row * 512, 512u,  mb);
                BULK1D(dst + 768, a2 + row * 512, 1024u, mb);
            }
        }
    };

    if (tid == 0) { fill(0, 0); fill(1, 1); fill(2, 2); }

    float4 sA = F4Z, sB = F4Z, sC = F4Z, sD = F4Z;
    float4 tA = F4Z, tB = F4Z, tC = F4Z, tD = F4Z;

    #pragma unroll 1
    for (int i = 0; i < NITER; i++) {
        const int s  = i & (NST - 1);
        const uint32_t ph = (uint32_t)((i >> 2) & 1);
        mbar_wait(mb0 + 8 * s, ph);
        if (active) {
            #pragma unroll
            for (int r = 0; r < RPS; r++) {
                const float4 x = *reinterpret_cast<const float4*>(&buf[s][r][soff]);
                const int g = gsh[i * RPS + r];             // warp-uniform
                if      (g == 0) ACC8(sA, tA, x);
                else if (g == 1) ACC8(sB, tB, x);
                else if (g == 2) ACC8(sC, tC, x);
                else             ACC8(sD, tD, x);
            }
        }
        __syncthreads();                                    // stage s free
        if (tid == 0 && i + 3 < NITER) fill(i + 3, (i + 3) & (NST - 1));
    }

    // Store partials (idle slots store zeros: scratch fully rewritten).
    const int base = (chunk * 4) * NSLOT + slot;
    g_Spart[base + 0 * NSLOT] = sA;
    g_Spart[base + 1 * NSLOT] = sB;
    g_Spart[base + 2 * NSLOT] = sC;
    g_Spart[base + 3 * NSLOT] = sD;
    g_Qpart[base + 0 * NSLOT] = tA.x + tA.y + tA.z + tA.w;
    g_Qpart[base + 1 * NSLOT] = tB.x + tB.y + tB.z + tB.w;
    g_Qpart[base + 2 * NSLOT] = tC.x + tC.y + tC.z + tC.w;
    g_Qpart[base + 3 * NSLOT] = tD.x + tD.y + tD.z + tD.w;
}

// ---------------------------------------------------------------------------
// kB: slot-major chunk reduction -> single fully reduced plane (L2 hits).
// grid = 48 x 128. Block owns 8 slots; (t&7)=slot-local, (t>>3)=part(16);
// each part sums KB_CPP chunks; shared combine.
// ---------------------------------------------------------------------------
__global__ __launch_bounds__(128) void kB_reduce() {
    const int tid  = threadIdx.x;
    const int sl   = tid & 7;
    const int part = tid >> 3;
    const int slot = blockIdx.x * 8 + sl;

    float4 s[4] = {F4Z, F4Z, F4Z, F4Z};
    float  q[4] = {0.f, 0.f, 0.f, 0.f};
    const int c0 = part * KB_CPP;
    #pragma unroll
    for (int c = 0; c < KB_CPP; c++) {
        const int b = ((c0 + c) * 4) * NSLOT + slot;
        f4add(s[0], g_Spart[b + 0 * NSLOT]);
        f4add(s[1], g_Spart[b + 1 * NSLOT]);
        f4add(s[2], g_Spart[b + 2 * NSLOT]);
        f4add(s[3], g_Spart[b + 3 * NSLOT]);
        q[0] += g_Qpart[b + 0 * NSLOT];
        q[1] += g_Qpart[b + 1 * NSLOT];
        q[2] += g_Qpart[b + 2 * NSLOT];
        q[3] += g_Qpart[b + 3 * NSLOT];
    }

    __shared__ float4 shS[128][4];
    __shared__ float  shQ[128][4];
    #pragma unroll
    for (int g = 0; g < 4; g++) { shS[tid][g] = s[g]; shQ[tid][g] = q[g]; }
    __syncthreads();

    if (tid < 32) {
        const int csl = tid & 7, g = tid >> 3;
        float4 S = F4Z; float Q = 0.f;
        #pragma unroll
        for (int p = 0; p < KB_PART; p++) {
            f4add(S, shS[p * 8 + csl][g]);
            Q += shQ[p * 8 + csl][g];
        }
        const int oslot = blockIdx.x * 8 + csl;
        g_S2[g * NSLOT + oslot] = S;
        g_Q2[g * NSLOT + oslot] = Q;
    }
}

// ---------------------------------------------------------------------------
// kC: finalize. 1 block x 384 (12 warps); thread = slot; warp-uniform matrix.
// Warps 0-7 -> m0(rep,1024); warp 8 -> m1(act0,64); warp 9 -> m2(act1,128);
// warps 10-11 -> m3(act2,256). Pad slots carry zeros.
// ---------------------------------------------------------------------------
__global__ __launch_bounds__(384) void kC_final(
    const int* __restrict__ nl, float* __restrict__ out, int out_size)
{
    const int tid = threadIdx.x, lane = tid & 31, warp = tid >> 5;

    float4 S[4]; float q[4];
    #pragma unroll
    for (int g = 0; g < 4; g++) {
        S[g] = g_S2[g * NSLOT + tid];
        q[g] = g_Q2[g * NSLOT + tid];
    }

    double v[9];
    float4 st = F4Z;
    #pragma unroll
    for (int g = 0; g < 4; g++) {
        v[g] = (double)S[g].x * S[g].x + (double)S[g].y * S[g].y
             + (double)S[g].z * S[g].z + (double)S[g].w * S[g].w;
        v[4 + g] = (double)q[g];
        f4add(st, S[g]);
    }
    v[8] = (double)st.x * st.x + (double)st.y * st.y
         + (double)st.z * st.z + (double)st.w * st.w;

    __shared__ double wr[12][9];
    #pragma unroll
    for (int k = 0; k < 9; k++) {
        double x = v[k];
        #pragma unroll
        for (int off = 16; off > 0; off >>= 1) x += __shfl_down_sync(FULL, x, off);
        if (lane == 0) wr[warp][k] = x;
    }

    const int is64 = detect_int64(nl, tid, 384);   // barrier inside
    int c[4] = {0, 0, 0, 0};
    for (int i = tid; i < NB; i += 384) {
        const int g = (is64 ? nl[2 * i] : nl[i]) & 3;
        c[g]++;
    }
    __shared__ int cw[4][12];
    __shared__ int cnt_sh[4];
    #pragma unroll
    for (int g = 0; g < 4; g++) {
        int x = c[g];
        #pragma unroll
        for (int off = 16; off > 0; off >>= 1) x += __shfl_down_sync(FULL, x, off);
        if (lane == 0) cw[g][warp] = x;
    }
    __syncthreads();
    if (tid < 4) {
        int t = 0;
        #pragma unroll
        for (int w = 0; w < 12; w++) t += cw[tid][w];
        cnt_sh[tid] = t;
    }
    __syncthreads();

    if (tid == 0) {
        double msq[16], qm[16], Msq[4];
        #pragma unroll
        for (int k = 0; k < 16; k++) { msq[k] = 0.0; qm[k] = 0.0; }
        #pragma unroll
        for (int m = 0; m < 4; m++) Msq[m] = 0.0;
        #pragma unroll
        for (int w = 0; w < 12; w++) {
            const int m = (w < 8) ? 0 : (w == 8) ? 1 : (w == 9) ? 2 : 3;
            #pragma unroll
            for (int g = 0; g < 4; g++) {
                msq[m * 4 + g] += wr[w][g];
                qm [m * 4 + g] += wr[w][4 + g];
            }
            Msq[m] += wr[w][8];
        }

        double n[4], cpos = 0.0;
        #pragma unroll
        for (int g = 0; g < 4; g++) {
            n[g] = (double)cnt_sh[g];
            cpos += 0.5 * n[g] * (n[g] - 1.0);
        }
        const double Bv = (double)NB;
        const double cneg = 0.5 * Bv * (Bv - 1.0) - cpos;
        const double icp = 1.0 / cpos, icn = 1.0 / cneg;
        const double idm[4] = {1.0/1024.0, 1.0/64.0, 1.0/128.0, 1.0/256.0};

        double loss[4];
        #pragma unroll
        for (int m = 0; m < 4; m++) {
            double Spos = 0.0, Q = 0.0;
            #pragma unroll
            for (int g = 0; g < 4; g++) {
                Spos += n[g] * qm[m * 4 + g] - msq[m * 4 + g];
                Q    += qm[m * 4 + g];
            }
            Spos *= idm[m];
            const double Sall = (Bv * Q - Msq[m]) * idm[m];
            const double Sneg = Sall - Spos;
            loss[m] = Spos * icp - Sneg * icn;
        }
        const double latent = (loss[1] + loss[2] + loss[3]) * (1.0 / 3.0);
        out[0] = (float)(0.5 * latent + 0.5 * loss[0]);      // W = 0.5
    }
    for (int i = 1 + tid; i < out_size; i += 384) out[i] = 0.0f;
}

// ---------------------------------------------------------------------------
extern "C" void kernel_launch(void* const* d_in, const int* in_sizes, int n_in,
                              void* d_out, int out_size) {
    const float* rep = (const float*)d_in[0];
    const float* a0  = (const float*)d_in[1];
    const float* a1  = (const float*)d_in[2];
    const float* a2  = (const float*)d_in[3];
    const int*   nl  = (const int*)d_in[4];

    kA_partial<<<dim3(3, NCHUNK), 128>>>(rep, a0, a1, a2, nl);
    kB_reduce<<<KB_BLK, 128>>>();
    kC_final<<<1, 384>>>(nl, (float*)d_out, out_size);
}

// round 13
// speedup vs baseline: 1.4313x; 1.4313x over previous
#include <cuda_runtime.h>
#include <cstdint>

// ---------------------------------------------------------------------------
// DisentanglementModule loss, closed form (TAU_POS == TAU_NEG => tau cancels):
//   loss_x = S_pos/c_pos - S_neg/c_neg
//   S_pos  = sum_g (n_g * q_g - ||m_g||^2) / d
//   S_all  = (B * Q - ||M||^2) / d ,  S_neg = S_all - S_pos
// Column-separable: per-column per-group sums (m) + sums-of-squares (q).
//
// Flattened column space: 384 float4 "slots", warp-aligned per matrix:
//   slots [0,256)    rep  (1024 cols)                 warps 0-7
//   slots [256,272)  act0 (64 cols); [272,288) pad    warp 8
//   slots [288,320)  act1 (128 cols)                  warp 9
//   slots [320,384)  act2 (256 cols)                  warps 10-11
//
// kA: grid (3,128). cp.async 4-stage ring, DEPTH-3 in flight (24KB/block);
//     threads consume only their own staged 16B -> no barriers in the loop.
// kBC: 48 blocks reduce chunk partials -> reduced plane; LAST block (atomic
//     ticket, deterministic fixed-order combines) finalizes the loss.
// ---------------------------------------------------------------------------

#define NB      4096
#define NCHUNK  128
#define RPC     32                  // rows per chunk (NCHUNK*RPC == NB)
#define NSTAGE  8                   // pipeline stages per chunk (4 rows each)
#define NSLOT   384
#define KB_BLK  48
#define KB_PART 16
#define KB_CPP  (NCHUNK / KB_PART)  // 8
#define FULL    0xFFFFFFFFu

// Scratch: every element rewritten each launch; g_ctr re-armed by last block
// -> graph-replay safe. No float atomics anywhere (deterministic).
__device__ __align__(16) float4 g_Spart[NCHUNK * 4 * NSLOT]; // 3.1MB
__device__ float  g_Qpart[NCHUNK * 4 * NSLOT];               // 786KB
__device__ __align__(16) float4 g_S2[4 * NSLOT];             // 24KB
__device__ float  g_Q2[4 * NSLOT];                           // 6KB
__device__ int    g_ctr = 0;

#define F4Z make_float4(0.f, 0.f, 0.f, 0.f)
__device__ __forceinline__ void f4add(float4& a, const float4 b) {
    a.x += b.x; a.y += b.y; a.z += b.z; a.w += b.w;
}

#define CPASYNC16(sa, ga) \
    asm volatile("cp.async.cg.shared.global [%0], [%1], 16;" :: "r"(sa), "l"(ga))
#define CPCOMMIT()  asm volatile("cp.async.commit_group;" ::: "memory")
#define CPWAIT2()   asm volatile("cp.async.wait_group 2;" ::: "memory")
#define CPWAIT1()   asm volatile("cp.async.wait_group 1;" ::: "memory")
#define CPWAIT0()   asm volatile("cp.async.wait_group 0;" ::: "memory")

// int64-vs-int32 detection: values in [0,3]; if int64 (LE), odd words are 0
// and even words <= 3. Vote over first 1024 pairs via __syncthreads_count.
__device__ __forceinline__ int detect_int64(const int* __restrict__ nl, int tid, int nthr) {
    int bad = 0;
    for (int i = tid; i < 1024; i += nthr) {
        const int lo = nl[2 * i], hi = nl[2 * i + 1];
        if (hi != 0 || (unsigned)lo > 3u) bad = 1;
    }
    return __syncthreads_count(bad) == 0;
}

// ---------------------------------------------------------------------------
// kA: cp.async deep-pipelined streaming. grid=(3, NCHUNK), 128 thr = slots.
// ---------------------------------------------------------------------------
#define ACC8(S, T, x) do {                                   \
    S.x += x.x; S.y += x.y; S.z += x.z; S.w += x.w;          \
    T.x = fmaf(x.x, x.x, T.x); T.y = fmaf(x.y, x.y, T.y);    \
    T.z = fmaf(x.z, x.z, T.z); T.w = fmaf(x.w, x.w, T.w); } while (0)

__global__ __launch_bounds__(128) void kA_partial(
    const float* __restrict__ rep, const float* __restrict__ a0,
    const float* __restrict__ a1,  const float* __restrict__ a2,
    const int* __restrict__ nl)
{
    __shared__ float4 buf[4][4][128];            // 32KB, 4-stage ring x 4 rows
    const int tid   = threadIdx.x;
    const int slot  = blockIdx.x * 128 + tid;
    const int chunk = blockIdx.y;
    const int row0  = chunk * RPC;

    const int is64 = detect_int64(nl, tid, 128); // barrier inside
    __shared__ int gsh[RPC];
    if (tid < RPC)
        gsh[tid] = (is64 ? nl[2 * (row0 + tid)] : nl[row0 + tid]) & 3;
    __syncthreads();

    // Slot -> (src, ld, col). act2 owns [320,384) fully; pad = [272,288).
    const float* src; int ld, col, active = 1;
    if (slot < 256)      { src = rep; ld = 1024; col = slot * 4; }
    else if (slot < 272) { src = a0;  ld = 512;  col = (slot - 256) * 4; }
    else if (slot < 288) { src = a0;  ld = 512;  col = 0; active = 0; }  // pad
    else if (slot < 320) { src = a1;  ld = 512;  col = (slot - 288) * 4; }
    else                 { src = a2;  ld = 512;  col = (slot - 320) * 4; }

    const float* p = src + (size_t)row0 * ld + col;
    const uint32_t sbase = (uint32_t)__cvta_generic_to_shared(&buf[0][0][tid]);
    // ring stage s (0..3), row r (0..3) -> sbase + (s*4 + r) * 2048

    float4 sA = F4Z, sB = F4Z, sC = F4Z, sD = F4Z;
    float4 tA = F4Z, tB = F4Z, tC = F4Z, tD = F4Z;

    // Prologue: commit stages 0..2 -> 3 groups (24KB/block) in flight.
    #pragma unroll
    for (int s = 0; s < 3; s++) {
        if (active) {
            #pragma unroll
            for (int r = 0; r < 4; r++)
                CPASYNC16(sbase + (s * 4 + r) * 2048, p + (size_t)(s * 4 + r) * ld);
        }
        CPCOMMIT();
    }

    #pragma unroll
    for (int i = 0; i < NSTAGE; i++) {
        // Ensure stage i has landed (pending after completion = min(2, 7-i)).
        if (i < 6)      CPWAIT2();
        else if (i == 6) CPWAIT1();
        else             CPWAIT0();

        // Refill: commit stage i+3 into ring buffer (i+3)&3 (= (i-1)&3,
        // consumed by this thread at iter i-1; per-thread self-use -> safe).
        if (i + 3 < NSTAGE) {
            if (active) {
                const int b1 = (i + 3) & 3;
                #pragma unroll
                for (int r = 0; r < 4; r++)
                    CPASYNC16(sbase + (b1 * 4 + r) * 2048,
                              p + (size_t)((i + 3) * 4 + r) * ld);
            }
            CPCOMMIT();
        }

        if (active) {
            const int b = i & 3;
            #pragma unroll
            for (int r = 0; r < 4; r++) {
                const float4 x = buf[b][r][tid];
                const int g = gsh[i * 4 + r];               // warp-uniform
                if      (g == 0) ACC8(sA, tA, x);
                else if (g == 1) ACC8(sB, tB, x);
                else if (g == 2) ACC8(sC, tC, x);
                else             ACC8(sD, tD, x);
            }
        }
    }

    // Store partials (idle slots store zeros: scratch fully rewritten).
    const int base = (chunk * 4) * NSLOT + slot;
    g_Spart[base + 0 * NSLOT] = sA;
    g_Spart[base + 1 * NSLOT] = sB;
    g_Spart[base + 2 * NSLOT] = sC;
    g_Spart[base + 3 * NSLOT] = sD;
    g_Qpart[base + 0 * NSLOT] = tA.x + tA.y + tA.z + tA.w;
    g_Qpart[base + 1 * NSLOT] = tB.x + tB.y + tB.z + tB.w;
    g_Qpart[base + 2 * NSLOT] = tC.x + tC.y + tC.z + tC.w;
    g_Qpart[base + 3 * NSLOT] = tD.x + tD.y + tD.z + tD.w;
}

// ---------------------------------------------------------------------------
// kBC: reduce + finalize. grid = 48 x 128.
// Phase 1 (all blocks): block owns 8 slots; (t&7)=slot-local, (t>>3)=part;
//   each part sums KB_CPP chunks; shared combine -> g_S2/g_Q2 plane.
// Phase 2 (last block by atomic ticket): finalize loss. 3 passes of 128
//   threads produce the same 12 warp-entries as the old 384-thread kC:
//   entries 0-7 -> m0, 8 -> m1(+pad zeros), 9 -> m2, 10-11 -> m3.
// ---------------------------------------------------------------------------
__global__ __launch_bounds__(128) void kBC_reduce_final(
    const int* __restrict__ nl, float* __restrict__ out, int out_size)
{
    const int tid  = threadIdx.x;
    const int sl   = tid & 7;
    const int part = tid >> 3;
    const int slot = blockIdx.x * 8 + sl;
    const int lane = tid & 31, warp = tid >> 5;

    float4 s[4] = {F4Z, F4Z, F4Z, F4Z};
    float  q[4] = {0.f, 0.f, 0.f, 0.f};
    const int c0 = part * KB_CPP;
    #pragma unroll
    for (int c = 0; c < KB_CPP; c++) {
        const int b = ((c0 + c) * 4) * NSLOT + slot;
        f4add(s[0], g_Spart[b + 0 * NSLOT]);
        f4add(s[1], g_Spart[b + 1 * NSLOT]);
        f4add(s[2], g_Spart[b + 2 * NSLOT]);
        f4add(s[3], g_Spart[b + 3 * NSLOT]);
        q[0] += g_Qpart[b + 0 * NSLOT];
        q[1] += g_Qpart[b + 1 * NSLOT];
        q[2] += g_Qpart[b + 2 * NSLOT];
        q[3] += g_Qpart[b + 3 * NSLOT];
    }

    __shared__ float4 shS[128][4];
    __shared__ float  shQ[128][4];
    #pragma unroll
    for (int g = 0; g < 4; g++) { shS[tid][g] = s[g]; shQ[tid][g] = q[g]; }
    __syncthreads();

    if (tid < 32) {
        const int csl = tid & 7, g = tid >> 3;
        float4 S = F4Z; float Q = 0.f;
        #pragma unroll
        for (int p = 0; p < KB_PART; p++) {
            f4add(S, shS[p * 8 + csl][g]);
            Q += shQ[p * 8 + csl][g];
        }
        const int oslot = blockIdx.x * 8 + csl;
        g_S2[g * NSLOT + oslot] = S;
        g_Q2[g * NSLOT + oslot] = Q;
    }

    // ---- last-block ticket (arrive-and-exit; no spin, no deadlock) ----
    __threadfence();
    __shared__ int ticket;
    __syncthreads();                  // writes above done before tid0 arrives
    if (tid == 0) ticket = atomicAdd(&g_ctr, 1);
    __syncthreads();
    if (ticket != KB_BLK - 1) return;
    __threadfence();                  // other blocks' g_S2/g_Q2 now visible

    // ---- finalize (128 threads, 3 slot passes) ----
    __shared__ double wr[12][9];
    #pragma unroll
    for (int ps = 0; ps < 3; ps++) {
        const int fslot = ps * 128 + tid;
        float4 S[4]; float fq[4];
        #pragma unroll
        for (int g = 0; g < 4; g++) {
            S[g]  = g_S2[g * NSLOT + fslot];
            fq[g] = g_Q2[g * NSLOT + fslot];
        }
        double v[9];
        float4 st = F4Z;
        #pragma unroll
        for (int g = 0; g < 4; g++) {
            v[g] = (double)S[g].x * S[g].x + (double)S[g].y * S[g].y
                 + (double)S[g].z * S[g].z + (double)S[g].w * S[g].w;
            v[4 + g] = (double)fq[g];
            f4add(st, S[g]);
        }
        v[8] = (double)st.x * st.x + (double)st.y * st.y
             + (double)st.z * st.z + (double)st.w * st.w;
        #pragma unroll
        for (int k = 0; k < 9; k++) {
            double x = v[k];
            #pragma unroll
            for (int off = 16; off > 0; off >>= 1)
                x += __shfl_down_sync(FULL, x, off);
            if (lane == 0) wr[ps * 4 + warp][k] = x;
        }
    }

    // Group counts (detect has a barrier inside, also orders wr writes).
    const int is64 = detect_int64(nl, tid, 128);
    int c[4] = {0, 0, 0, 0};
    for (int i = tid; i < NB; i += 128) {
        const int g = (is64 ? nl[2 * i] : nl[i]) & 3;
        c[g]++;
    }
    __shared__ int cw[4][4];
    __shared__ int cnt_sh[4];
    #pragma unroll
    for (int g = 0; g < 4; g++) {
        int x = c[g];
        #pragma unroll
        for (int off = 16; off > 0; off >>= 1) x += __shfl_down_sync(FULL, x, off);
        if (lane == 0) cw[g][warp] = x;
    }
    __syncthreads();
    if (tid < 4) cnt_sh[tid] = cw[tid][0] + cw[tid][1] + cw[tid][2] + cw[tid][3];
    __syncthreads();

    if (tid == 0) {
        double msq[16], qm[16], Msq[4];
        #pragma unroll
        for (int k = 0; k < 16; k++) { msq[k] = 0.0; qm[k] = 0.0; }
        #pragma unroll
        for (int m = 0; m < 4; m++) Msq[m] = 0.0;
        #pragma unroll
        for (int w = 0; w < 12; w++) {
            const int m = (w < 8) ? 0 : (w == 8) ? 1 : (w == 9) ? 2 : 3;
            #pragma unroll
            for (int g = 0; g < 4; g++) {
                msq[m * 4 + g] += wr[w][g];
                qm [m * 4 + g] += wr[w][4 + g];
            }
            Msq[m] += wr[w][8];
        }

        double n[4], cpos = 0.0;
        #pragma unroll
        for (int g = 0; g < 4; g++) {
            n[g] = (double)cnt_sh[g];
            cpos += 0.5 * n[g] * (n[g] - 1.0);
        }
        const double Bv = (double)NB;
        const double cneg = 0.5 * Bv * (Bv - 1.0) - cpos;
        const double icp = 1.0 / cpos, icn = 1.0 / cneg;
        const double idm[4] = {1.0/1024.0, 1.0/64.0, 1.0/128.0, 1.0/256.0};

        double loss[4];
        #pragma unroll
        for (int m = 0; m < 4; m++) {
            double Spos = 0.0, Q = 0.0;
            #pragma unroll
            for (int g = 0; g < 4; g++) {
                Spos += n[g] * qm[m * 4 + g] - msq[m * 4 + g];
                Q    += qm[m * 4 + g];
            }
            Spos *= idm[m];
            const double Sall = (Bv * Q - Msq[m]) * idm[m];
            const double Sneg = Sall - Spos;
            loss[m] = Spos * icp - Sneg * icn;
        }
        const double latent = (loss[1] + loss[2] + loss[3]) * (1.0 / 3.0);
        out[0] = (float)(0.5 * latent + 0.5 * loss[0]);      // W = 0.5
        g_ctr = 0;                                           // re-arm for replay
    }
    for (int i = 1 + tid; i < out_size; i += 128) out[i] = 0.0f;
}

// ---------------------------------------------------------------------------
extern "C" void kernel_launch(void* const* d_in, const int* in_sizes, int n_in,
                              void* d_out, int out_size) {
    const float* rep = (const float*)d_in[0];
    const float* a0  = (const float*)d_in[1];
    const float* a1  = (const float*)d_in[2];
    const float* a2  = (const float*)d_in[3];
    const int*   nl  = (const int*)d_in[4];

    kA_partial<<<dim3(3, NCHUNK), 128>>>(rep, a0, a1, a2, nl);
    kBC_reduce_final<<<KB_BLK, 128>>>(nl, (float*)d_out, out_size);
}